// round 3
// baseline (speedup 1.0000x reference)
#include <cuda_runtime.h>
#include <cuda_bf16.h>
#include <cstdint>
#include <cstddef>

// ---------------------------------------------------------------------------
// Decoder: out = (x - diag(t_mlp(z))) * exp(-diag(s_mlp(z))), z = koopman^T
// bf16 hi/lo split GEMMs (3-term) via mma.sync m16n8k16, fp32 accumulate.
// ---------------------------------------------------------------------------

static constexpr int B_  = 2048;
static constexpr int D_  = 64;
static constexpr int R_  = B_ * D_;       // 131072 rows

#define BM   128
#define BN   128
#define BKC  32
#define SPAD 40   // padded smem row stride (elems): 80B, conflict-free frag loads

static constexpr size_t SZ_Z   = (size_t)R_ * 64 * 2;
static constexpr size_t SZ_H   = (size_t)R_ * 512 * 2;
static constexpr size_t SZ_DS  = (size_t)R_ * 4;
static constexpr size_t WT_ELEMS = 32768 + 262144 + 262144;
static constexpr size_t SZ_WT  = WT_ELEMS * 2;
static constexpr size_t SZ_W4T = (size_t)64 * 512 * 4;

static constexpr size_t OFF_ZH   = 0;
static constexpr size_t OFF_ZL   = OFF_ZH  + SZ_Z;
static constexpr size_t OFF_H0H  = OFF_ZL  + SZ_Z;
static constexpr size_t OFF_H0L  = OFF_H0H + SZ_H;
static constexpr size_t OFF_H1H  = OFF_H0L + SZ_H;
static constexpr size_t OFF_H1L  = OFF_H1H + SZ_H;
static constexpr size_t OFF_DS   = OFF_H1L + SZ_H;
static constexpr size_t OFF_WTH0 = OFF_DS   + SZ_DS;
static constexpr size_t OFF_WTL0 = OFF_WTH0 + SZ_WT;
static constexpr size_t OFF_WTH1 = OFF_WTL0 + SZ_WT;
static constexpr size_t OFF_WTL1 = OFF_WTH1 + SZ_WT;
static constexpr size_t OFF_W4T0 = OFF_WTL1 + SZ_WT;
static constexpr size_t OFF_W4T1 = OFF_W4T0 + SZ_W4T;
static constexpr size_t SCRATCH_BYTES = OFF_W4T1 + SZ_W4T;

__device__ __align__(256) unsigned char g_scratch[SCRATCH_BYTES];

static constexpr size_t WOFF_1 = 0;
static constexpr size_t WOFF_2 = 32768;
static constexpr size_t WOFF_3 = 294912;

__device__ __forceinline__ void cp16(uint32_t s, const void* g) {
    asm volatile("cp.async.cg.shared.global [%0], [%1], 16;\n" :: "r"(s), "l"(g));
}
__device__ __forceinline__ void cp_commit() {
    asm volatile("cp.async.commit_group;\n");
}
__device__ __forceinline__ void mma16816(float c[4], const uint32_t a[4], const uint32_t b[2]) {
    asm volatile(
        "mma.sync.aligned.m16n8k16.row.col.f32.bf16.bf16.f32 "
        "{%0,%1,%2,%3}, {%4,%5,%6,%7}, {%8,%9}, {%0,%1,%2,%3};\n"
        : "+f"(c[0]), "+f"(c[1]), "+f"(c[2]), "+f"(c[3])
        : "r"(a[0]), "r"(a[1]), "r"(a[2]), "r"(a[3]), "r"(b[0]), "r"(b[1]));
}
__device__ __forceinline__ void split2(float v, __nv_bfloat16& hi, __nv_bfloat16& lo) {
    hi = __float2bfloat16(v);
    lo = __float2bfloat16(v - __bfloat162float(hi));
}

// --------------------------- prep kernels ----------------------------------

__global__ void split_z_kernel(const float* __restrict__ koop) {
    __nv_bfloat16* Zh = (__nv_bfloat16*)(g_scratch + OFF_ZH);
    __nv_bfloat16* Zl = (__nv_bfloat16*)(g_scratch + OFF_ZL);
    __shared__ float s[64][65];
    int b = blockIdx.x;
    const float* src = koop + (size_t)b * 4096;
    for (int t = threadIdx.x; t < 4096; t += 256) {
        int l = t >> 6, i = t & 63;
        s[l][i] = src[t];
    }
    __syncthreads();
    for (int t = threadIdx.x; t < 4096; t += 256) {
        int i = t >> 6, l = t & 63;
        float v = s[l][i];
        __nv_bfloat16 h, lo; split2(v, h, lo);
        size_t o = (size_t)(b * 64 + i) * 64 + l;
        Zh[o] = h; Zl[o] = lo;
    }
}

__global__ void split_weight(const float* __restrict__ W, size_t offH, size_t offL,
                             size_t elemOff, int fi, int fo) {
    __nv_bfloat16* Wth = (__nv_bfloat16*)(g_scratch + offH) + elemOff;
    __nv_bfloat16* Wtl = (__nv_bfloat16*)(g_scratch + offL) + elemOff;
    int idx = blockIdx.x * blockDim.x + threadIdx.x;
    if (idx >= fi * fo) return;
    int n = idx / fi, k = idx - n * fi;
    float v = W[(size_t)k * fo + n];
    __nv_bfloat16 h, lo; split2(v, h, lo);
    Wth[idx] = h; Wtl[idx] = lo;
}

__global__ void transpose_w4(const float* __restrict__ W4, size_t offOut) {
    float* W4t = (float*)(g_scratch + offOut);
    int idx = blockIdx.x * blockDim.x + threadIdx.x;
    if (idx >= 64 * 512) return;
    int d = idx >> 9, k = idx & 511;
    W4t[idx] = W4[(size_t)k * 64 + d];
}

// --------------------------- GEMM ------------------------------------------

__device__ __forceinline__ void load_tiles(__nv_bfloat16* smem, int st, int k0,
                                           int rowCTA, int colCTA, int K,
                                           const __nv_bfloat16* Ah, const __nv_bfloat16* Al,
                                           const __nv_bfloat16* Bth, const __nv_bfloat16* Btl) {
    uint32_t sbase = (uint32_t)__cvta_generic_to_shared(smem);
    #pragma unroll
    for (int it = 0; it < 2; ++it) {
        int idx = it * 256 + threadIdx.x;
        int row = idx >> 2;
        int sc  = (idx & 3) * 8;
        uint32_t o = sbase + (uint32_t)st * (BM * SPAD * 2)
                           + (uint32_t)row * (SPAD * 2) + (uint32_t)sc * 2;
        const size_t ga = (size_t)(rowCTA + row) * K + k0 + sc;
        const size_t gb = (size_t)(colCTA + row) * K + k0 + sc;
        cp16(o,          Ah  + ga);
        cp16(o + 20480u, Al  + ga);
        cp16(o + 40960u, Bth + gb);
        cp16(o + 61440u, Btl + gb);
    }
}

__global__ void __launch_bounds__(256, 1)
gemm_tanh_split(size_t offAh, size_t offAl,
                size_t offBth, size_t offBtl, size_t wElemOff,
                const float* __restrict__ bias,
                size_t offCh, size_t offCl, int K) {
    const __nv_bfloat16* Ah  = (const __nv_bfloat16*)(g_scratch + offAh);
    const __nv_bfloat16* Al  = (const __nv_bfloat16*)(g_scratch + offAl);
    const __nv_bfloat16* Bth = (const __nv_bfloat16*)(g_scratch + offBth) + wElemOff;
    const __nv_bfloat16* Btl = (const __nv_bfloat16*)(g_scratch + offBtl) + wElemOff;
    __nv_bfloat16* Ch = (__nv_bfloat16*)(g_scratch + offCh);
    __nv_bfloat16* Cl = (__nv_bfloat16*)(g_scratch + offCl);

    extern __shared__ __align__(16) __nv_bfloat16 smem[];

    const int tid  = threadIdx.x;
    const int warp = tid >> 5, lane = tid & 31;
    const int wm = warp & 1, wn = warp >> 1;
    const int g  = lane >> 2, tg = lane & 3;
    const int rowCTA = blockIdx.y * BM;
    const int colCTA = blockIdx.x * BN;

    float acc[4][4][4];
    #pragma unroll
    for (int a = 0; a < 4; ++a)
        #pragma unroll
        for (int b = 0; b < 4; ++b)
            #pragma unroll
            for (int c = 0; c < 4; ++c) acc[a][b][c] = 0.f;

    const int nk = K / BKC;
    load_tiles(smem, 0, 0, rowCTA, colCTA, K, Ah, Al, Bth, Btl);
    cp_commit();

    for (int kk = 0; kk < nk; ++kk) {
        if (kk + 1 < nk) {
            load_tiles(smem, (kk + 1) & 1, (kk + 1) * BKC, rowCTA, colCTA, K, Ah, Al, Bth, Btl);
            cp_commit();
            asm volatile("cp.async.wait_group 1;\n");
        } else {
            asm volatile("cp.async.wait_group 0;\n");
        }
        __syncthreads();

        const int st = kk & 1;
        const __nv_bfloat16* pAh = smem + (size_t)st * BM * SPAD;
        const __nv_bfloat16* pAl = pAh + 2 * BM * SPAD;
        const __nv_bfloat16* pBh = pAh + 4 * BM * SPAD;
        const __nv_bfloat16* pBl = pAh + 6 * BM * SPAD;

        #pragma unroll
        for (int kh = 0; kh < 2; ++kh) {
            const int k16 = kh * 16 + 2 * tg;
            uint32_t afh[4][4], afl[4][4];
            #pragma unroll
            for (int mt = 0; mt < 4; ++mt) {
                const int r0 = (wm * 64 + mt * 16 + g) * SPAD + k16;
                const __nv_bfloat16* p = pAh + r0;
                const __nv_bfloat16* q = pAl + r0;
                afh[mt][0] = *(const uint32_t*)(p);
                afh[mt][1] = *(const uint32_t*)(p + 8 * SPAD);
                afh[mt][2] = *(const uint32_t*)(p + 8);
                afh[mt][3] = *(const uint32_t*)(p + 8 * SPAD + 8);
                afl[mt][0] = *(const uint32_t*)(q);
                afl[mt][1] = *(const uint32_t*)(q + 8 * SPAD);
                afl[mt][2] = *(const uint32_t*)(q + 8);
                afl[mt][3] = *(const uint32_t*)(q + 8 * SPAD + 8);
            }
            #pragma unroll
            for (int nt = 0; nt < 4; ++nt) {
                const int c0 = (wn * 32 + nt * 8 + g) * SPAD + k16;
                const __nv_bfloat16* pb = pBh + c0;
                const __nv_bfloat16* qb = pBl + c0;
                uint32_t bh[2] = { *(const uint32_t*)(pb), *(const uint32_t*)(pb + 8) };
                uint32_t bl[2] = { *(const uint32_t*)(qb), *(const uint32_t*)(qb + 8) };
                #pragma unroll
                for (int mt = 0; mt < 4; ++mt) {
                    mma16816(acc[mt][nt], afh[mt], bh);
                    mma16816(acc[mt][nt], afh[mt], bl);
                    mma16816(acc[mt][nt], afl[mt], bh);
                }
            }
        }
        __syncthreads();
    }

    #pragma unroll
    for (int mt = 0; mt < 4; ++mt) {
        const int r0 = rowCTA + wm * 64 + mt * 16 + g;
        #pragma unroll
        for (int nt = 0; nt < 4; ++nt) {
            const int c = colCTA + wn * 32 + nt * 8 + 2 * tg;
            const float bb0 = bias[c], bb1 = bias[c + 1];
            #pragma unroll
            for (int h = 0; h < 2; ++h) {
                const int r = r0 + h * 8;
                float v0 = tanhf(acc[mt][nt][2 * h + 0] + bb0);
                float v1 = tanhf(acc[mt][nt][2 * h + 1] + bb1);
                __nv_bfloat16 h0, l0, h1, l1;
                split2(v0, h0, l0); split2(v1, h1, l1);
                size_t off = (size_t)r * 512 + c;
                *reinterpret_cast<__nv_bfloat162*>(Ch + off) = __halves2bfloat162(h0, h1);
                *reinterpret_cast<__nv_bfloat162*>(Cl + off) = __halves2bfloat162(l0, l1);
            }
        }
    }
}

// --------------------------- layer-4 diagonal ------------------------------

__global__ void diag_kernel(size_t offHh, size_t offHl, size_t offW4t,
                            const float* __restrict__ b4,
                            const float* __restrict__ x,
                            float* __restrict__ out, int mode) {
    const __nv_bfloat16* Hhp = (const __nv_bfloat16*)(g_scratch + offHh);
    const __nv_bfloat16* Hlp = (const __nv_bfloat16*)(g_scratch + offHl);
    const float* W4t = (const float*)(g_scratch + offW4t);
    float* ds = (float*)(g_scratch + OFF_DS);

    int warpid = (blockIdx.x * blockDim.x + threadIdx.x) >> 5;
    int lane = threadIdx.x & 31;
    if (warpid >= R_) return;
    int r = warpid;
    int i = r & 63;
    const __nv_bfloat16* ph = Hhp + (size_t)r * 512;
    const __nv_bfloat16* pl = Hlp + (size_t)r * 512;
    const float* w = W4t + (size_t)i * 512;
    float acc = 0.f;
    #pragma unroll
    for (int k = lane; k < 512; k += 32)
        acc += (__bfloat162float(ph[k]) + __bfloat162float(pl[k])) * w[k];
    #pragma unroll
    for (int o = 16; o; o >>= 1) acc += __shfl_xor_sync(0xffffffffu, acc, o);
    if (lane == 0) {
        float v = acc + b4[i];
        if (mode == 0) ds[r] = v;
        else           out[r] = (x[r] - v) * expf(-ds[r]);
    }
}

// --------------------------- launch ----------------------------------------

extern "C" void kernel_launch(void* const* d_in, const int* in_sizes, int n_in,
                              void* d_out, int out_size) {
    (void)in_sizes; (void)n_in; (void)out_size;
    const float* x    = (const float*)d_in[0];
    const float* koop = (const float*)d_in[1];
    const float* W1[2] = { (const float*)d_in[2],  (const float*)d_in[10] };
    const float* b1[2] = { (const float*)d_in[3],  (const float*)d_in[11] };
    const float* W2[2] = { (const float*)d_in[4],  (const float*)d_in[12] };
    const float* b2[2] = { (const float*)d_in[5],  (const float*)d_in[13] };
    const float* W3[2] = { (const float*)d_in[6],  (const float*)d_in[14] };
    const float* b3[2] = { (const float*)d_in[7],  (const float*)d_in[15] };
    const float* W4[2] = { (const float*)d_in[8],  (const float*)d_in[16] };
    const float* b4[2] = { (const float*)d_in[9],  (const float*)d_in[17] };
    float* out = (float*)d_out;

    const int SMEM_BYTES = 8 * BM * SPAD * 2;  // 81920
    cudaFuncSetAttribute((const void*)gemm_tanh_split,
                         cudaFuncAttributeMaxDynamicSharedMemorySize, SMEM_BYTES);

    const size_t WTH[2] = { OFF_WTH0, OFF_WTH1 };
    const size_t WTL[2] = { OFF_WTL0, OFF_WTL1 };
    const size_t W4T[2] = { OFF_W4T0, OFF_W4T1 };

    split_z_kernel<<<B_, 256>>>(koop);
    for (int m = 0; m < 2; ++m) {
        split_weight<<<(32768  + 255) / 256, 256>>>(W1[m], WTH[m], WTL[m], WOFF_1, 64, 512);
        split_weight<<<(262144 + 255) / 256, 256>>>(W2[m], WTH[m], WTL[m], WOFF_2, 512, 512);
        split_weight<<<(262144 + 255) / 256, 256>>>(W3[m], WTH[m], WTL[m], WOFF_3, 512, 512);
        transpose_w4<<<(32768 + 255) / 256, 256>>>(W4[m], W4T[m]);
    }

    dim3 grid(512 / BN, R_ / BM);
    for (int m = 0; m < 2; ++m) {
        gemm_tanh_split<<<grid, 256, SMEM_BYTES>>>(OFF_ZH, OFF_ZL,
            WTH[m], WTL[m], WOFF_1, b1[m], OFF_H0H, OFF_H0L, 64);
        gemm_tanh_split<<<grid, 256, SMEM_BYTES>>>(OFF_H0H, OFF_H0L,
            WTH[m], WTL[m], WOFF_2, b2[m], OFF_H1H, OFF_H1L, 512);
        gemm_tanh_split<<<grid, 256, SMEM_BYTES>>>(OFF_H1H, OFF_H1L,
            WTH[m], WTL[m], WOFF_3, b3[m], OFF_H0H, OFF_H0L, 512);
        diag_kernel<<<R_ / 8, 256>>>(OFF_H0H, OFF_H0L, W4T[m], b4[m], x, out, m);
    }
}

// round 5
// speedup vs baseline: 2.1546x; 2.1546x over previous
#include <cuda_runtime.h>
#include <cuda_bf16.h>
#include <cstdint>
#include <cstddef>

// ---------------------------------------------------------------------------
// Decoder: out = (x - diag(t_mlp(z))) * exp(-diag(s_mlp(z))), z = koopman^T
// tcgen05 SS-mode bf16 hi/lo-split GEMMs (sm_103a cubin) with an mma.sync
// fallback body for non-'a' virtual-arch compilation passes.
// ---------------------------------------------------------------------------

#if defined(__CUDA_ARCH__) && (__CUDA_ARCH__ >= 1000) && \
    (defined(__CUDA_ARCH_FEAT_SM103_ALL) || defined(__CUDA_ARCH_FEAT_SM100_ALL) || \
     defined(__CUDA_ARCH_SPECIFIC__))
#define TC_OK 1
#else
#define TC_OK 0
#endif

static constexpr int B_  = 2048;
static constexpr int R_  = B_ * 64;       // 131072 rows

static constexpr size_t SZ_Z   = (size_t)R_ * 64 * 2;
static constexpr size_t SZ_H   = (size_t)R_ * 512 * 2;
static constexpr size_t SZ_DS  = (size_t)R_ * 4;
static constexpr size_t WT_ELEMS = 32768 + 262144 + 262144;
static constexpr size_t SZ_WT  = WT_ELEMS * 2;
static constexpr size_t SZ_W4T = (size_t)64 * 512 * 4;

static constexpr size_t OFF_ZH   = 0;
static constexpr size_t OFF_ZL   = OFF_ZH  + SZ_Z;
static constexpr size_t OFF_H0H  = OFF_ZL  + SZ_Z;
static constexpr size_t OFF_H0L  = OFF_H0H + SZ_H;
static constexpr size_t OFF_H1H  = OFF_H0L + SZ_H;
static constexpr size_t OFF_H1L  = OFF_H1H + SZ_H;
static constexpr size_t OFF_DS   = OFF_H1L + SZ_H;
static constexpr size_t OFF_WTH0 = OFF_DS   + SZ_DS;
static constexpr size_t OFF_WTL0 = OFF_WTH0 + SZ_WT;
static constexpr size_t OFF_WTH1 = OFF_WTL0 + SZ_WT;
static constexpr size_t OFF_WTL1 = OFF_WTH1 + SZ_WT;
static constexpr size_t OFF_W4T0 = OFF_WTL1 + SZ_WT;
static constexpr size_t OFF_W4T1 = OFF_W4T0 + SZ_W4T;
static constexpr size_t SCRATCH_BYTES = OFF_W4T1 + SZ_W4T;

__device__ __align__(256) unsigned char g_scratch[SCRATCH_BYTES];

static constexpr size_t WOFF_1 = 0;
static constexpr size_t WOFF_2 = 32768;
static constexpr size_t WOFF_3 = 294912;

// ---------------------------------------------------------------------------
// common helpers
// ---------------------------------------------------------------------------
__device__ __forceinline__ void cp16(uint32_t s, const void* g) {
    asm volatile("cp.async.cg.shared.global [%0], [%1], 16;\n" :: "r"(s), "l"(g));
}
__device__ __forceinline__ void cp_commit() {
    asm volatile("cp.async.commit_group;\n");
}
__device__ __forceinline__ void split2(float v, __nv_bfloat16& hi, __nv_bfloat16& lo) {
    hi = __float2bfloat16(v);
    lo = __float2bfloat16(v - __bfloat162float(hi));
}
__device__ __forceinline__ uint32_t smem_u32(const void* p) {
    return (uint32_t)__cvta_generic_to_shared(p);
}

// ---------------------------------------------------------------------------
// tcgen05 helpers (feature-gated)
// ---------------------------------------------------------------------------
#if TC_OK
__device__ __forceinline__ uint32_t elect_one_pred() {
    uint32_t pred;
    asm volatile(
        "{\n\t.reg .pred p;\n\t"
        "elect.sync _|p, 0xFFFFFFFF;\n\t"
        "selp.b32 %0, 1, 0, p;\n\t}"
        : "=r"(pred));
    return pred;
}
__device__ __forceinline__ void mbar_init(uint32_t mbar, uint32_t cnt) {
    asm volatile("mbarrier.init.shared.b64 [%0], %1;" :: "r"(mbar), "r"(cnt) : "memory");
}
__device__ __forceinline__ void mbar_inval(uint32_t mbar) {
    asm volatile("mbarrier.inval.shared.b64 [%0];" :: "r"(mbar) : "memory");
}
__device__ __forceinline__ void mbar_wait(uint32_t mbar, uint32_t parity) {
    asm volatile(
        "{\n\t.reg .pred P1;\n\t"
        "WAIT_LOOP_%=:\n\t"
        "mbarrier.try_wait.parity.acquire.cta.shared::cta.b64 P1, [%0], %1, 0x989680;\n\t"
        "@P1 bra.uni WAIT_DONE_%=;\n\t"
        "bra.uni WAIT_LOOP_%=;\n\t"
        "WAIT_DONE_%=:\n\t}"
        :: "r"(mbar), "r"(parity) : "memory");
}
__device__ __forceinline__ void tcgen05_commit(uint32_t mbar) {
    asm volatile(
        "tcgen05.commit.cta_group::1.mbarrier::arrive::one.shared::cluster.b64 [%0];"
        :: "r"(mbar) : "memory");
}
__device__ __forceinline__ void fence_proxy_async_cta() {
    asm volatile("fence.proxy.async.shared::cta;" ::: "memory");
}

// SW128 K-major smem descriptor (layout=2, version=1, SBO=64, LBO=1)
static constexpr uint64_t SMEM_DESC_BASE_SW128 =
    (uint64_t(2)  << 61) | (uint64_t(1) << 46) | (uint64_t(64) << 32) | (uint64_t(1) << 16);
__device__ __forceinline__ uint64_t make_desc(uint32_t addr) {
    return SMEM_DESC_BASE_SW128 | ((uint64_t)(addr >> 4) & 0x3FFF);
}

// idesc: dtype F32, a/b BF16, N=256, M=128, cta_group::1
static constexpr uint32_t IDESC_F16 =
    (1u << 4) | (1u << 7) | (1u << 10) | ((256u / 8u) << 17) | ((128u / 16u) << 24);

__device__ __forceinline__ void mma_f16_ss(uint32_t d_tmem, uint64_t a_desc,
                                           uint64_t b_desc, uint32_t en) {
    asm volatile(
        "{\n\t.reg .pred p;\n\t"
        "setp.ne.u32 p, %4, 0;\n\t"
        "tcgen05.mma.cta_group::1.kind::f16 [%0], %1, %2, %3, {%5,%5,%5,%5}, p;\n\t}"
        :: "r"(d_tmem), "l"(a_desc), "l"(b_desc), "r"(IDESC_F16), "r"(en), "r"(0u)
        : "memory");
}

#define TC_ALLOC(dst_smem, n) \
    asm volatile("tcgen05.alloc.cta_group::1.sync.aligned.shared::cta.b32 [%0], %1;" \
                 :: "r"(dst_smem), "r"((uint32_t)(n)) : "memory")
#define TC_DEALLOC(tmem, n) \
    asm volatile("tcgen05.dealloc.cta_group::1.sync.aligned.b32 %0, %1;" \
                 :: "r"(tmem), "r"((uint32_t)(n)))
#define TC_FENCE_AFTER()  asm volatile("tcgen05.fence::after_thread_sync;" ::: "memory")
#define TC_FENCE_BEFORE() asm volatile("tcgen05.fence::before_thread_sync;" ::: "memory")
#define TC_WAIT_LD()      asm volatile("tcgen05.wait::ld.sync.aligned;" ::: "memory")

#define TC_LD_X32(r, addr) \
    asm volatile( \
        "tcgen05.ld.sync.aligned.32x32b.x32.b32 " \
        "{%0, %1, %2, %3, %4, %5, %6, %7, " \
        " %8, %9, %10, %11, %12, %13, %14, %15, " \
        " %16, %17, %18, %19, %20, %21, %22, %23, " \
        " %24, %25, %26, %27, %28, %29, %30, %31}, [%32];" \
        : "=r"((r)[0]),  "=r"((r)[1]),  "=r"((r)[2]),  "=r"((r)[3]), \
          "=r"((r)[4]),  "=r"((r)[5]),  "=r"((r)[6]),  "=r"((r)[7]), \
          "=r"((r)[8]),  "=r"((r)[9]),  "=r"((r)[10]), "=r"((r)[11]), \
          "=r"((r)[12]), "=r"((r)[13]), "=r"((r)[14]), "=r"((r)[15]), \
          "=r"((r)[16]), "=r"((r)[17]), "=r"((r)[18]), "=r"((r)[19]), \
          "=r"((r)[20]), "=r"((r)[21]), "=r"((r)[22]), "=r"((r)[23]), \
          "=r"((r)[24]), "=r"((r)[25]), "=r"((r)[26]), "=r"((r)[27]), \
          "=r"((r)[28]), "=r"((r)[29]), "=r"((r)[30]), "=r"((r)[31]) \
        : "r"(addr))
#endif  // TC_OK

// ---------------------------------------------------------------------------
// mma.sync fallback helper (always compiled; harmless if unused)
// ---------------------------------------------------------------------------
__device__ __forceinline__ void mma16816(float c[4], const uint32_t a[4], const uint32_t b[2]) {
    asm volatile(
        "mma.sync.aligned.m16n8k16.row.col.f32.bf16.bf16.f32 "
        "{%0,%1,%2,%3}, {%4,%5,%6,%7}, {%8,%9}, {%0,%1,%2,%3};\n"
        : "+f"(c[0]), "+f"(c[1]), "+f"(c[2]), "+f"(c[3])
        : "r"(a[0]), "r"(a[1]), "r"(a[2]), "r"(a[3]), "r"(b[0]), "r"(b[1]));
}

// ---------------------------------------------------------------------------
// prep kernels
// ---------------------------------------------------------------------------
__global__ void split_z_kernel(const float* __restrict__ koop) {
    __nv_bfloat16* Zh = (__nv_bfloat16*)(g_scratch + OFF_ZH);
    __nv_bfloat16* Zl = (__nv_bfloat16*)(g_scratch + OFF_ZL);
    __shared__ float s[64][65];
    int b = blockIdx.x;
    const float* src = koop + (size_t)b * 4096;
    for (int t = threadIdx.x; t < 4096; t += 256) {
        int l = t >> 6, i = t & 63;
        s[l][i] = src[t];
    }
    __syncthreads();
    for (int t = threadIdx.x; t < 4096; t += 256) {
        int i = t >> 6, l = t & 63;
        float v = s[l][i];
        __nv_bfloat16 h, lo; split2(v, h, lo);
        size_t o = (size_t)(b * 64 + i) * 64 + l;
        Zh[o] = h; Zl[o] = lo;
    }
}

__global__ void split_weight(const float* __restrict__ W, size_t offH, size_t offL,
                             size_t elemOff, int fi, int fo) {
    __nv_bfloat16* Wth = (__nv_bfloat16*)(g_scratch + offH) + elemOff;
    __nv_bfloat16* Wtl = (__nv_bfloat16*)(g_scratch + offL) + elemOff;
    int idx = blockIdx.x * blockDim.x + threadIdx.x;
    if (idx >= fi * fo) return;
    int n = idx / fi, k = idx - n * fi;
    float v = W[(size_t)k * fo + n];
    __nv_bfloat16 h, lo; split2(v, h, lo);
    Wth[idx] = h; Wtl[idx] = lo;
}

__global__ void transpose_w4(const float* __restrict__ W4, size_t offOut) {
    float* W4t = (float*)(g_scratch + offOut);
    int idx = blockIdx.x * blockDim.x + threadIdx.x;
    if (idx >= 64 * 512) return;
    int d = idx >> 9, k = idx & 511;
    W4t[idx] = W4[(size_t)k * 64 + d];
}

// ---------------------------------------------------------------------------
// GEMM: C = split(tanh(A @ Bt^T + bias))
// A: (R_, K) bf16 hi/lo; Bt: (512, K) bf16 hi/lo; CTA tile M=128, N=256.
// ---------------------------------------------------------------------------
static constexpr uint32_t STG_A_H = 0;
static constexpr uint32_t STG_A_L = 16384;
static constexpr uint32_t STG_B_H = 32768;
static constexpr uint32_t STG_B_L = 65536;
static constexpr uint32_t STG_SZ  = 98304;
static constexpr int GEMM_SMEM = 2 * 98304 + 1024;   // 197632

#if TC_OK
__device__ __forceinline__ void load_stage(uint32_t tile, int st, int k0,
                                           int rowCTA, int colCTA, int K,
                                           const __nv_bfloat16* Ah, const __nv_bfloat16* Al,
                                           const __nv_bfloat16* Bh, const __nv_bfloat16* Bl) {
    const uint32_t base = tile + (uint32_t)st * STG_SZ;
    const int tid = threadIdx.x;
    #pragma unroll
    for (int j = 0; j < 4; ++j) {            // A: 128 rows x 128B (SW128)
        int idx = tid + 256 * j;
        int row = idx >> 3, c16 = idx & 7;
        uint32_t boff = (uint32_t)(row * 128 + c16 * 16);
        uint32_t sw = boff ^ ((boff >> 3) & 0x70);
        const size_t g = (size_t)(rowCTA + row) * K + k0 + c16 * 8;
        cp16(base + STG_A_H + sw, Ah + g);
        cp16(base + STG_A_L + sw, Al + g);
    }
    #pragma unroll
    for (int j = 0; j < 8; ++j) {            // B: 256 rows x 128B (SW128)
        int idx = tid + 256 * j;
        int row = idx >> 3, c16 = idx & 7;
        uint32_t boff = (uint32_t)(row * 128 + c16 * 16);
        uint32_t sw = boff ^ ((boff >> 3) & 0x70);
        const size_t g = (size_t)(colCTA + row) * K + k0 + c16 * 8;
        cp16(base + STG_B_H + sw, Bh + g);
        cp16(base + STG_B_L + sw, Bl + g);
    }
}
#else
// fallback smem loader (R2 layout: 2 stages x {Ah,Al,Bh,Bl} of 128x40 bf16)
__device__ __forceinline__ void load_tiles_fb(__nv_bfloat16* smem, int st, int k0,
                                              int rowCTA, int colCTA, int K,
                                              const __nv_bfloat16* Ah, const __nv_bfloat16* Al,
                                              const __nv_bfloat16* Bth, const __nv_bfloat16* Btl) {
    uint32_t sbase = smem_u32(smem);
    #pragma unroll
    for (int it = 0; it < 2; ++it) {
        int idx = it * 256 + threadIdx.x;
        int row = idx >> 2;
        int sc  = (idx & 3) * 8;
        uint32_t o = sbase + (uint32_t)st * (128 * 40 * 2)
                           + (uint32_t)row * (40 * 2) + (uint32_t)sc * 2;
        const size_t ga = (size_t)(rowCTA + row) * K + k0 + sc;
        const size_t gb = (size_t)(colCTA + row) * K + k0 + sc;
        cp16(o,          Ah  + ga);
        cp16(o + 20480u, Al  + ga);
        cp16(o + 40960u, Bth + gb);
        cp16(o + 61440u, Btl + gb);
    }
}
#endif

__global__ void __launch_bounds__(256, 1)
gemm_t5(size_t offAh, size_t offAl, size_t offBth, size_t offBtl, size_t wElemOff,
        const float* __restrict__ bias, size_t offCh, size_t offCl, int K) {
    const __nv_bfloat16* Ah  = (const __nv_bfloat16*)(g_scratch + offAh);
    const __nv_bfloat16* Al  = (const __nv_bfloat16*)(g_scratch + offAl);
    const __nv_bfloat16* Bth = (const __nv_bfloat16*)(g_scratch + offBth) + wElemOff;
    const __nv_bfloat16* Btl = (const __nv_bfloat16*)(g_scratch + offBtl) + wElemOff;
    __nv_bfloat16* Ch = (__nv_bfloat16*)(g_scratch + offCh);
    __nv_bfloat16* Cl = (__nv_bfloat16*)(g_scratch + offCl);

#if TC_OK
    // =======================  tcgen05 path  =======================
    extern __shared__ __align__(16) unsigned char dyn[];
    __shared__ __align__(16) uint32_t s_ctrl[4];     // [0] = tmem base
    __shared__ __align__(8)  uint64_t s_mbar;
    __shared__ float sbias[256];

    const int tid  = threadIdx.x;
    const int warp = tid >> 5, lane = tid & 31;
    const int rowCTA = blockIdx.y * 128;
    const int colCTA = blockIdx.x * 256;

    const uint32_t tile = (smem_u32(dyn) + 1023u) & ~1023u;
    const uint32_t ctrl = smem_u32(s_ctrl);
    const uint32_t mbar = smem_u32(&s_mbar);

    sbias[tid] = bias[colCTA + tid];

    if (warp == 0) TC_ALLOC(ctrl, 256);
    if (tid == 0) mbar_init(mbar, 1);

    const int nk = K >> 6;
    load_stage(tile, 0, 0, rowCTA, colCTA, K, Ah, Al, Bth, Btl);
    cp_commit();
    __syncthreads();
    const uint32_t tmem = s_ctrl[0];

    for (int i = 0; i < nk; ++i) {
        if (i + 1 < nk) {
            if (i >= 1) mbar_wait(mbar, (uint32_t)((i - 1) & 1));  // MMA i-1 done
            load_stage(tile, (i + 1) & 1, (i + 1) * 64, rowCTA, colCTA, K, Ah, Al, Bth, Btl);
            cp_commit();
            asm volatile("cp.async.wait_group 1;\n" ::: "memory");
        } else {
            asm volatile("cp.async.wait_group 0;\n" ::: "memory");
        }
        fence_proxy_async_cta();
        __syncthreads();

        if (warp == 0 && elect_one_pred()) {
            const uint32_t sa = tile + (uint32_t)(i & 1) * STG_SZ;
            const uint64_t dAh = make_desc(sa + STG_A_H);
            const uint64_t dAl = make_desc(sa + STG_A_L);
            const uint64_t dBh = make_desc(sa + STG_B_H);
            const uint64_t dBl = make_desc(sa + STG_B_L);
            #pragma unroll
            for (int ks = 0; ks < 4; ++ks) {
                const uint64_t ko = (uint64_t)(ks * 2);
                mma_f16_ss(tmem, dAh + ko, dBh + ko, (i > 0 || ks > 0) ? 1u : 0u);
                mma_f16_ss(tmem, dAh + ko, dBl + ko, 1u);
                mma_f16_ss(tmem, dAl + ko, dBh + ko, 1u);
            }
            tcgen05_commit(mbar);
        }
    }

    if (nk >= 2) mbar_wait(mbar, (uint32_t)((nk - 2) & 1));
    mbar_wait(mbar, (uint32_t)((nk - 1) & 1));
    TC_FENCE_AFTER();

    // epilogue: bias + tanh + hi/lo split; 8 warps x (32 rows, 128 cols)
    {
        const int sub = warp & 3;
        const int colbase = (warp >> 2) * 128;
        const int row = rowCTA + sub * 32 + lane;
        #pragma unroll
        for (int cc = 0; cc < 4; ++cc) {
            const int c0 = colbase + cc * 32;
            uint32_t r[32];
            TC_LD_X32(r, tmem + (uint32_t)c0);
            TC_WAIT_LD();
            uint32_t ph[16], pl[16];
            #pragma unroll
            for (int c = 0; c < 32; c += 2) {
                float v0 = tanhf(__uint_as_float(r[c])     + sbias[c0 + c]);
                float v1 = tanhf(__uint_as_float(r[c + 1]) + sbias[c0 + c + 1]);
                __nv_bfloat16 h0, l0, h1, l1;
                split2(v0, h0, l0); split2(v1, h1, l1);
                __nv_bfloat162 th = __halves2bfloat162(h0, h1);
                __nv_bfloat162 tl = __halves2bfloat162(l0, l1);
                ph[c >> 1] = *reinterpret_cast<uint32_t*>(&th);
                pl[c >> 1] = *reinterpret_cast<uint32_t*>(&tl);
            }
            const size_t o = (size_t)row * 512 + colCTA + c0;
            uint4* dh = reinterpret_cast<uint4*>(Ch + o);
            uint4* dl = reinterpret_cast<uint4*>(Cl + o);
            #pragma unroll
            for (int q = 0; q < 4; ++q) {
                dh[q] = make_uint4(ph[4 * q], ph[4 * q + 1], ph[4 * q + 2], ph[4 * q + 3]);
                dl[q] = make_uint4(pl[4 * q], pl[4 * q + 1], pl[4 * q + 2], pl[4 * q + 3]);
            }
        }
        TC_FENCE_BEFORE();
    }

    __syncthreads();
    if (tid == 0) mbar_inval(mbar);
    __syncthreads();
    if (warp == 0) TC_DEALLOC(tmem, 256);

#else
    // =======================  mma.sync fallback  =======================
    extern __shared__ __align__(16) __nv_bfloat16 smem[];
    const int tid  = threadIdx.x;
    const int warp = tid >> 5, lane = tid & 31;
    const int wm = warp & 1, wn = warp >> 1;
    const int g  = lane >> 2, tg = lane & 3;
    const int rowCTA = blockIdx.y * 128;

    for (int nh = 0; nh < 2; ++nh) {
        const int colCTA = blockIdx.x * 256 + nh * 128;

        float acc[4][4][4];
        #pragma unroll
        for (int a = 0; a < 4; ++a)
            #pragma unroll
            for (int b = 0; b < 4; ++b)
                #pragma unroll
                for (int c = 0; c < 4; ++c) acc[a][b][c] = 0.f;

        const int nk = K / 32;
        __syncthreads();
        load_tiles_fb(smem, 0, 0, rowCTA, colCTA, K, Ah, Al, Bth, Btl);
        cp_commit();

        for (int kk = 0; kk < nk; ++kk) {
            if (kk + 1 < nk) {
                load_tiles_fb(smem, (kk + 1) & 1, (kk + 1) * 32, rowCTA, colCTA, K, Ah, Al, Bth, Btl);
                cp_commit();
                asm volatile("cp.async.wait_group 1;\n");
            } else {
                asm volatile("cp.async.wait_group 0;\n");
            }
            __syncthreads();

            const int st = kk & 1;
            const __nv_bfloat16* pAh = smem + (size_t)st * 128 * 40;
            const __nv_bfloat16* pAl = pAh + 2 * 128 * 40;
            const __nv_bfloat16* pBh = pAh + 4 * 128 * 40;
            const __nv_bfloat16* pBl = pAh + 6 * 128 * 40;

            #pragma unroll
            for (int kh = 0; kh < 2; ++kh) {
                const int k16 = kh * 16 + 2 * tg;
                uint32_t afh[4][4], afl[4][4];
                #pragma unroll
                for (int mt = 0; mt < 4; ++mt) {
                    const int r0 = (wm * 64 + mt * 16 + g) * 40 + k16;
                    const __nv_bfloat16* p = pAh + r0;
                    const __nv_bfloat16* q = pAl + r0;
                    afh[mt][0] = *(const uint32_t*)(p);
                    afh[mt][1] = *(const uint32_t*)(p + 8 * 40);
                    afh[mt][2] = *(const uint32_t*)(p + 8);
                    afh[mt][3] = *(const uint32_t*)(p + 8 * 40 + 8);
                    afl[mt][0] = *(const uint32_t*)(q);
                    afl[mt][1] = *(const uint32_t*)(q + 8 * 40);
                    afl[mt][2] = *(const uint32_t*)(q + 8);
                    afl[mt][3] = *(const uint32_t*)(q + 8 * 40 + 8);
                }
                #pragma unroll
                for (int nt = 0; nt < 4; ++nt) {
                    const int c0 = (wn * 32 + nt * 8 + g) * 40 + k16;
                    const __nv_bfloat16* pb = pBh + c0;
                    const __nv_bfloat16* qb = pBl + c0;
                    uint32_t bh[2] = { *(const uint32_t*)(pb), *(const uint32_t*)(pb + 8) };
                    uint32_t bl[2] = { *(const uint32_t*)(qb), *(const uint32_t*)(qb + 8) };
                    #pragma unroll
                    for (int mt = 0; mt < 4; ++mt) {
                        mma16816(acc[mt][nt], afh[mt], bh);
                        mma16816(acc[mt][nt], afh[mt], bl);
                        mma16816(acc[mt][nt], afl[mt], bh);
                    }
                }
            }
            __syncthreads();
        }

        #pragma unroll
        for (int mt = 0; mt < 4; ++mt) {
            const int r0 = rowCTA + wm * 64 + mt * 16 + g;
            #pragma unroll
            for (int nt = 0; nt < 4; ++nt) {
                const int c = colCTA + wn * 32 + nt * 8 + 2 * tg;
                const float bb0 = bias[c], bb1 = bias[c + 1];
                #pragma unroll
                for (int h = 0; h < 2; ++h) {
                    const int r = r0 + h * 8;
                    float v0 = tanhf(acc[mt][nt][2 * h + 0] + bb0);
                    float v1 = tanhf(acc[mt][nt][2 * h + 1] + bb1);
                    __nv_bfloat16 h0, l0, h1, l1;
                    split2(v0, h0, l0); split2(v1, h1, l1);
                    size_t off = (size_t)r * 512 + c;
                    *reinterpret_cast<__nv_bfloat162*>(Ch + off) = __halves2bfloat162(h0, h1);
                    *reinterpret_cast<__nv_bfloat162*>(Cl + off) = __halves2bfloat162(l0, l1);
                }
            }
        }
    }
#endif
}

// ---------------------------------------------------------------------------
// layer-4 diagonal
// ---------------------------------------------------------------------------
__global__ void diag_kernel(size_t offHh, size_t offHl, size_t offW4t,
                            const float* __restrict__ b4,
                            const float* __restrict__ x,
                            float* __restrict__ out, int mode) {
    const __nv_bfloat16* Hhp = (const __nv_bfloat16*)(g_scratch + offHh);
    const __nv_bfloat16* Hlp = (const __nv_bfloat16*)(g_scratch + offHl);
    const float* W4t = (const float*)(g_scratch + offW4t);
    float* ds = (float*)(g_scratch + OFF_DS);

    int warpid = (blockIdx.x * blockDim.x + threadIdx.x) >> 5;
    int lane = threadIdx.x & 31;
    if (warpid >= R_) return;
    int r = warpid;
    int i = r & 63;
    const __nv_bfloat16* ph = Hhp + (size_t)r * 512;
    const __nv_bfloat16* pl = Hlp + (size_t)r * 512;
    const float* w = W4t + (size_t)i * 512;
    float acc = 0.f;
    #pragma unroll
    for (int k = lane; k < 512; k += 32)
        acc += (__bfloat162float(ph[k]) + __bfloat162float(pl[k])) * w[k];
    #pragma unroll
    for (int o = 16; o; o >>= 1) acc += __shfl_xor_sync(0xffffffffu, acc, o);
    if (lane == 0) {
        float v = acc + b4[i];
        if (mode == 0) ds[r] = v;
        else           out[r] = (x[r] - v) * expf(-ds[r]);
    }
}

// ---------------------------------------------------------------------------
// launch
// ---------------------------------------------------------------------------
extern "C" void kernel_launch(void* const* d_in, const int* in_sizes, int n_in,
                              void* d_out, int out_size) {
    (void)in_sizes; (void)n_in; (void)out_size;
    const float* x    = (const float*)d_in[0];
    const float* koop = (const float*)d_in[1];
    const float* W1[2] = { (const float*)d_in[2],  (const float*)d_in[10] };
    const float* b1[2] = { (const float*)d_in[3],  (const float*)d_in[11] };
    const float* W2[2] = { (const float*)d_in[4],  (const float*)d_in[12] };
    const float* b2[2] = { (const float*)d_in[5],  (const float*)d_in[13] };
    const float* W3[2] = { (const float*)d_in[6],  (const float*)d_in[14] };
    const float* b3[2] = { (const float*)d_in[7],  (const float*)d_in[15] };
    const float* W4[2] = { (const float*)d_in[8],  (const float*)d_in[16] };
    const float* b4[2] = { (const float*)d_in[9],  (const float*)d_in[17] };
    float* out = (float*)d_out;

    cudaFuncSetAttribute((const void*)gemm_t5,
                         cudaFuncAttributeMaxDynamicSharedMemorySize, GEMM_SMEM);

    const size_t WTH[2] = { OFF_WTH0, OFF_WTH1 };
    const size_t WTL[2] = { OFF_WTL0, OFF_WTL1 };
    const size_t W4T[2] = { OFF_W4T0, OFF_W4T1 };

    split_z_kernel<<<B_, 256>>>(koop);
    for (int m = 0; m < 2; ++m) {
        split_weight<<<(32768  + 255) / 256, 256>>>(W1[m], WTH[m], WTL[m], WOFF_1, 64, 512);
        split_weight<<<(262144 + 255) / 256, 256>>>(W2[m], WTH[m], WTL[m], WOFF_2, 512, 512);
        split_weight<<<(262144 + 255) / 256, 256>>>(W3[m], WTH[m], WTL[m], WOFF_3, 512, 512);
        transpose_w4<<<(32768 + 255) / 256, 256>>>(W4[m], W4T[m]);
    }

    dim3 grid(2, R_ / 128);   // N blocks x M blocks
    for (int m = 0; m < 2; ++m) {
        gemm_t5<<<grid, 256, GEMM_SMEM>>>(OFF_ZH, OFF_ZL,
            WTH[m], WTL[m], WOFF_1, b1[m], OFF_H0H, OFF_H0L, 64);
        gemm_t5<<<grid, 256, GEMM_SMEM>>>(OFF_H0H, OFF_H0L,
            WTH[m], WTL[m], WOFF_2, b2[m], OFF_H1H, OFF_H1L, 512);
        gemm_t5<<<grid, 256, GEMM_SMEM>>>(OFF_H1H, OFF_H1L,
            WTH[m], WTL[m], WOFF_3, b3[m], OFF_H0H, OFF_H0L, 512);
        diag_kernel<<<R_ / 8, 256>>>(OFF_H0H, OFF_H0L, W4T[m], b4[m], x, out, m);
    }
}

// round 9
// speedup vs baseline: 2.1669x; 1.0057x over previous
#include <cuda_runtime.h>
#include <cuda_bf16.h>
#include <cstdint>
#include <cstddef>

// ---------------------------------------------------------------------------
// Decoder: out = (x - diag(t_mlp(z))) * exp(-diag(s_mlp(z))), z = koopman^T
// tcgen05 SS-mode bf16 hi/lo-split GEMMs; s/t MLPs merged into 1024-wide
// layers; layer-4 diagonal fused into the layer-3 epilogue (no layer-3 store).
// ---------------------------------------------------------------------------

#if defined(__CUDA_ARCH__) && (__CUDA_ARCH__ >= 1000) && \
    (defined(__CUDA_ARCH_FEAT_SM103_ALL) || defined(__CUDA_ARCH_FEAT_SM100_ALL) || \
     defined(__CUDA_ARCH_SPECIFIC__))
#define TC_OK 1
#else
#define TC_OK 0
#endif

static constexpr int B_  = 2048;
static constexpr int R_  = B_ * 64;        // 131072 rows
static constexpr int NW  = 1024;           // combined width (s|t)

static constexpr size_t SZ_Z   = (size_t)R_ * 64 * 2;          // bf16
static constexpr size_t SZ_H   = (size_t)R_ * NW * 2;          // bf16 (268MB)
static constexpr size_t SZ_DS  = (size_t)R_ * 4;
static constexpr size_t WT_ELEMS = (size_t)NW * 64 + (size_t)NW * 512 * 2;  // 1114112
static constexpr size_t SZ_WT  = WT_ELEMS * 2;
static constexpr size_t SZ_W4T = (size_t)2 * 64 * 512 * 4;     // both tables

static constexpr size_t OFF_ZH   = 0;
static constexpr size_t OFF_ZL   = OFF_ZH  + SZ_Z;
static constexpr size_t OFF_H0H  = OFF_ZL  + SZ_Z;
static constexpr size_t OFF_H0L  = OFF_H0H + SZ_H;
static constexpr size_t OFF_H1H  = OFF_H0L + SZ_H;
static constexpr size_t OFF_H1L  = OFF_H1H + SZ_H;
static constexpr size_t OFF_DS   = OFF_H1L + SZ_H;
static constexpr size_t OFF_DT   = OFF_DS  + SZ_DS;
static constexpr size_t OFF_WTH  = OFF_DT  + SZ_DS;
static constexpr size_t OFF_WTL  = OFF_WTH + SZ_WT;
static constexpr size_t OFF_W4T  = OFF_WTL + SZ_WT;
static constexpr size_t SCRATCH_BYTES = OFF_W4T + SZ_W4T;

__device__ __align__(256) unsigned char g_scratch[SCRATCH_BYTES];

// layer bases (elems) in the combined 1024-row weight regions
static constexpr size_t WOFF_1 = 0;                       // 1024 x 64
static constexpr size_t WOFF_2 = (size_t)NW * 64;         // 1024 x 512
static constexpr size_t WOFF_3 = WOFF_2 + (size_t)NW * 512;

// ---------------------------------------------------------------------------
// common helpers
// ---------------------------------------------------------------------------
__device__ __forceinline__ void cp16(uint32_t s, const void* g) {
    asm volatile("cp.async.cg.shared.global [%0], [%1], 16;\n" :: "r"(s), "l"(g));
}
__device__ __forceinline__ void cp_commit() {
    asm volatile("cp.async.commit_group;\n");
}
__device__ __forceinline__ void split2(float v, __nv_bfloat16& hi, __nv_bfloat16& lo) {
    hi = __float2bfloat16(v);
    lo = __float2bfloat16(v - __bfloat162float(hi));
}
__device__ __forceinline__ uint32_t smem_u32(const void* p) {
    return (uint32_t)__cvta_generic_to_shared(p);
}

// ---------------------------------------------------------------------------
// tcgen05 helpers (feature-gated)
// ---------------------------------------------------------------------------
#if TC_OK
__device__ __forceinline__ uint32_t elect_one_pred() {
    uint32_t pred;
    asm volatile(
        "{\n\t.reg .pred p;\n\t"
        "elect.sync _|p, 0xFFFFFFFF;\n\t"
        "selp.b32 %0, 1, 0, p;\n\t}"
        : "=r"(pred));
    return pred;
}
__device__ __forceinline__ void mbar_init(uint32_t mbar, uint32_t cnt) {
    asm volatile("mbarrier.init.shared.b64 [%0], %1;" :: "r"(mbar), "r"(cnt) : "memory");
}
__device__ __forceinline__ void mbar_inval(uint32_t mbar) {
    asm volatile("mbarrier.inval.shared.b64 [%0];" :: "r"(mbar) : "memory");
}
__device__ __forceinline__ void mbar_wait(uint32_t mbar, uint32_t parity) {
    asm volatile(
        "{\n\t.reg .pred P1;\n\t"
        "WAIT_LOOP_%=:\n\t"
        "mbarrier.try_wait.parity.acquire.cta.shared::cta.b64 P1, [%0], %1, 0x989680;\n\t"
        "@P1 bra.uni WAIT_DONE_%=;\n\t"
        "bra.uni WAIT_LOOP_%=;\n\t"
        "WAIT_DONE_%=:\n\t}"
        :: "r"(mbar), "r"(parity) : "memory");
}
__device__ __forceinline__ void tcgen05_commit(uint32_t mbar) {
    asm volatile(
        "tcgen05.commit.cta_group::1.mbarrier::arrive::one.shared::cluster.b64 [%0];"
        :: "r"(mbar) : "memory");
}
__device__ __forceinline__ void fence_proxy_async_cta() {
    asm volatile("fence.proxy.async.shared::cta;" ::: "memory");
}

static constexpr uint64_t SMEM_DESC_BASE_SW128 =
    (uint64_t(2)  << 61) | (uint64_t(1) << 46) | (uint64_t(64) << 32) | (uint64_t(1) << 16);
__device__ __forceinline__ uint64_t make_desc(uint32_t addr) {
    return SMEM_DESC_BASE_SW128 | ((uint64_t)(addr >> 4) & 0x3FFF);
}

// idesc: dtype F32, a/b BF16, N=256, M=128, cta_group::1
static constexpr uint32_t IDESC_F16 =
    (1u << 4) | (1u << 7) | (1u << 10) | ((256u / 8u) << 17) | ((128u / 16u) << 24);

__device__ __forceinline__ void mma_f16_ss(uint32_t d_tmem, uint64_t a_desc,
                                           uint64_t b_desc, uint32_t en) {
    asm volatile(
        "{\n\t.reg .pred p;\n\t"
        "setp.ne.u32 p, %4, 0;\n\t"
        "tcgen05.mma.cta_group::1.kind::f16 [%0], %1, %2, %3, {%5,%5,%5,%5}, p;\n\t}"
        :: "r"(d_tmem), "l"(a_desc), "l"(b_desc), "r"(IDESC_F16), "r"(en), "r"(0u)
        : "memory");
}

#define TC_ALLOC(dst_smem, n) \
    asm volatile("tcgen05.alloc.cta_group::1.sync.aligned.shared::cta.b32 [%0], %1;" \
                 :: "r"(dst_smem), "r"((uint32_t)(n)) : "memory")
#define TC_DEALLOC(tmem, n) \
    asm volatile("tcgen05.dealloc.cta_group::1.sync.aligned.b32 %0, %1;" \
                 :: "r"(tmem), "r"((uint32_t)(n)))
#define TC_FENCE_AFTER()  asm volatile("tcgen05.fence::after_thread_sync;" ::: "memory")
#define TC_FENCE_BEFORE() asm volatile("tcgen05.fence::before_thread_sync;" ::: "memory")
#define TC_WAIT_LD()      asm volatile("tcgen05.wait::ld.sync.aligned;" ::: "memory")

#define TC_LD_X32(r, addr) \
    asm volatile( \
        "tcgen05.ld.sync.aligned.32x32b.x32.b32 " \
        "{%0, %1, %2, %3, %4, %5, %6, %7, " \
        " %8, %9, %10, %11, %12, %13, %14, %15, " \
        " %16, %17, %18, %19, %20, %21, %22, %23, " \
        " %24, %25, %26, %27, %28, %29, %30, %31}, [%32];" \
        : "=r"((r)[0]),  "=r"((r)[1]),  "=r"((r)[2]),  "=r"((r)[3]), \
          "=r"((r)[4]),  "=r"((r)[5]),  "=r"((r)[6]),  "=r"((r)[7]), \
          "=r"((r)[8]),  "=r"((r)[9]),  "=r"((r)[10]), "=r"((r)[11]), \
          "=r"((r)[12]), "=r"((r)[13]), "=r"((r)[14]), "=r"((r)[15]), \
          "=r"((r)[16]), "=r"((r)[17]), "=r"((r)[18]), "=r"((r)[19]), \
          "=r"((r)[20]), "=r"((r)[21]), "=r"((r)[22]), "=r"((r)[23]), \
          "=r"((r)[24]), "=r"((r)[25]), "=r"((r)[26]), "=r"((r)[27]), \
          "=r"((r)[28]), "=r"((r)[29]), "=r"((r)[30]), "=r"((r)[31]) \
        : "r"(addr))
#endif  // TC_OK

__device__ __forceinline__ void mma16816(float c[4], const uint32_t a[4], const uint32_t b[2]) {
    asm volatile(
        "mma.sync.aligned.m16n8k16.row.col.f32.bf16.bf16.f32 "
        "{%0,%1,%2,%3}, {%4,%5,%6,%7}, {%8,%9}, {%0,%1,%2,%3};\n"
        : "+f"(c[0]), "+f"(c[1]), "+f"(c[2]), "+f"(c[3])
        : "r"(a[0]), "r"(a[1]), "r"(a[2]), "r"(a[3]), "r"(b[0]), "r"(b[1]));
}

// ---------------------------------------------------------------------------
// prep kernels
// ---------------------------------------------------------------------------
__global__ void split_z_kernel(const float* __restrict__ koop) {
    __nv_bfloat16* Zh = (__nv_bfloat16*)(g_scratch + OFF_ZH);
    __nv_bfloat16* Zl = (__nv_bfloat16*)(g_scratch + OFF_ZL);
    __shared__ float s[64][65];
    int b = blockIdx.x;
    const float* src = koop + (size_t)b * 4096;
    for (int t = threadIdx.x; t < 4096; t += 256) {
        int l = t >> 6, i = t & 63;
        s[l][i] = src[t];
    }
    __syncthreads();
    for (int t = threadIdx.x; t < 4096; t += 256) {
        int i = t >> 6, l = t & 63;
        float v = s[l][i];
        __nv_bfloat16 h, lo; split2(v, h, lo);
        size_t o = (size_t)(b * 64 + i) * 64 + l;
        Zh[o] = h; Zl[o] = lo;
    }
}

// W (fi x 512) fp32 -> rows [sel*512, sel*512+512) of combined (1024 x fi)
__global__ void split_weight(const float* __restrict__ W, size_t elemOff, int fi) {
    __nv_bfloat16* Wth = (__nv_bfloat16*)(g_scratch + OFF_WTH) + elemOff;
    __nv_bfloat16* Wtl = (__nv_bfloat16*)(g_scratch + OFF_WTL) + elemOff;
    int idx = blockIdx.x * blockDim.x + threadIdx.x;
    if (idx >= fi * 512) return;
    int n = idx / fi, k = idx - n * fi;
    float v = W[(size_t)k * 512 + n];
    __nv_bfloat16 h, lo; split2(v, h, lo);
    Wth[idx] = h; Wtl[idx] = lo;
}

// W4 (512 x 64) fp32 -> W4t (64 x 512) fp32, table sel
__global__ void transpose_w4(const float* __restrict__ W4, int sel) {
    float* W4t = (float*)(g_scratch + OFF_W4T) + (size_t)sel * 32768;
    int idx = blockIdx.x * blockDim.x + threadIdx.x;
    if (idx >= 64 * 512) return;
    int d = idx >> 9, k = idx & 511;
    W4t[idx] = W4[(size_t)k * 64 + d];
}

// ---------------------------------------------------------------------------
// GEMM: C = split(tanh(A @ Bt^T + bias)), or (diagMode) diag dot into ds/dt
// A: (R_, aLD) bf16 hi/lo, GEMM-K window starts at aColOff(colCTA)
// Bt: (1024, K) bf16 hi/lo combined; CTA tile M=128, N=256, grid (4, 1024)
// ---------------------------------------------------------------------------
static constexpr uint32_t STG_A_H = 0;
static constexpr uint32_t STG_A_L = 16384;
static constexpr uint32_t STG_B_H = 32768;
static constexpr uint32_t STG_B_L = 65536;
static constexpr uint32_t STG_SZ  = 98304;
static constexpr int GEMM_SMEM = 2 * 98304 + 1024;   // 197632

#if TC_OK
__device__ __forceinline__ void load_stage(uint32_t tile, int st, int k0,
                                           int rowCTA, int colCTA, int K, int aLD, int aColOff,
                                           const __nv_bfloat16* Ah, const __nv_bfloat16* Al,
                                           const __nv_bfloat16* Bh, const __nv_bfloat16* Bl) {
    const uint32_t base = tile + (uint32_t)st * STG_SZ;
    const int tid = threadIdx.x;
    #pragma unroll
    for (int j = 0; j < 4; ++j) {            // A: 128 rows x 128B (SW128)
        int idx = tid + 256 * j;
        int row = idx >> 3, c16 = idx & 7;
        uint32_t boff = (uint32_t)(row * 128 + c16 * 16);
        uint32_t sw = boff ^ ((boff >> 3) & 0x70);
        const size_t g = (size_t)(rowCTA + row) * aLD + aColOff + k0 + c16 * 8;
        cp16(base + STG_A_H + sw, Ah + g);
        cp16(base + STG_A_L + sw, Al + g);
    }
    #pragma unroll
    for (int j = 0; j < 8; ++j) {            // B: 256 rows x 128B (SW128)
        int idx = tid + 256 * j;
        int row = idx >> 3, c16 = idx & 7;
        uint32_t boff = (uint32_t)(row * 128 + c16 * 16);
        uint32_t sw = boff ^ ((boff >> 3) & 0x70);
        const size_t g = (size_t)(colCTA + row) * K + k0 + c16 * 8;
        cp16(base + STG_B_H + sw, Bh + g);
        cp16(base + STG_B_L + sw, Bl + g);
    }
}
#else
__device__ __forceinline__ void load_tiles_fb(__nv_bfloat16* smem, int st, int k0,
                                              int rowCTA, int colCTA, int K, int aLD, int aColOff,
                                              const __nv_bfloat16* Ah, const __nv_bfloat16* Al,
                                              const __nv_bfloat16* Bth, const __nv_bfloat16* Btl) {
    uint32_t sbase = smem_u32(smem);
    #pragma unroll
    for (int it = 0; it < 2; ++it) {
        int idx = it * 256 + threadIdx.x;
        int row = idx >> 2;
        int sc  = (idx & 3) * 8;
        uint32_t o = sbase + (uint32_t)st * (128 * 40 * 2)
                           + (uint32_t)row * (40 * 2) + (uint32_t)sc * 2;
        const size_t ga = (size_t)(rowCTA + row) * aLD + aColOff + k0 + sc;
        const size_t gb = (size_t)(colCTA + row) * K + k0 + sc;
        cp16(o,          Ah  + ga);
        cp16(o + 20480u, Al  + ga);
        cp16(o + 40960u, Bth + gb);
        cp16(o + 61440u, Btl + gb);
    }
}
#endif

__global__ void __launch_bounds__(256, 1)
gemm_t5(size_t offAh, size_t offAl, int aLD, int splitA, size_t wElemOff,
        const float* __restrict__ bias_s, const float* __restrict__ bias_t,
        size_t offCh, size_t offCl, int K, int diagMode) {
    const __nv_bfloat16* Ah  = (const __nv_bfloat16*)(g_scratch + offAh);
    const __nv_bfloat16* Al  = (const __nv_bfloat16*)(g_scratch + offAl);
    const __nv_bfloat16* Bth = (const __nv_bfloat16*)(g_scratch + OFF_WTH) + wElemOff;
    const __nv_bfloat16* Btl = (const __nv_bfloat16*)(g_scratch + OFF_WTL) + wElemOff;
    __nv_bfloat16* Ch = (__nv_bfloat16*)(g_scratch + offCh);
    __nv_bfloat16* Cl = (__nv_bfloat16*)(g_scratch + offCl);
    const float* W4T = (const float*)(g_scratch + OFF_W4T);
    float* dsbuf = (float*)(g_scratch + OFF_DS);
    float* dtbuf = (float*)(g_scratch + OFF_DT);

#if TC_OK
    // =======================  tcgen05 path  =======================
    extern __shared__ __align__(16) unsigned char dyn[];
    __shared__ __align__(16) uint32_t s_ctrl[4];     // [0] = tmem base
    __shared__ __align__(8)  uint64_t s_mbar;
    __shared__ float sbias[256];

    const int tid  = threadIdx.x;
    const int warp = tid >> 5, lane = tid & 31;
    const int rowCTA = blockIdx.y * 128;
    const int colCTA = blockIdx.x * 256;
    const int aColOff = splitA ? (colCTA & 512) : 0;

    const uint32_t tile = (smem_u32(dyn) + 1023u) & ~1023u;
    const uint32_t ctrl = smem_u32(s_ctrl);
    const uint32_t mbar = smem_u32(&s_mbar);

    {
        int c = colCTA + tid;
        sbias[tid] = (c < 512) ? bias_s[c] : bias_t[c - 512];
    }

    if (warp == 0) TC_ALLOC(ctrl, 256);
    if (tid == 0) mbar_init(mbar, 1);

    const int nk = K >> 6;
    load_stage(tile, 0, 0, rowCTA, colCTA, K, aLD, aColOff, Ah, Al, Bth, Btl);
    cp_commit();
    __syncthreads();
    const uint32_t tmem = s_ctrl[0];

    for (int i = 0; i < nk; ++i) {
        if (i + 1 < nk) {
            if (i >= 1) mbar_wait(mbar, (uint32_t)((i - 1) & 1));  // MMA i-1 done
            load_stage(tile, (i + 1) & 1, (i + 1) * 64, rowCTA, colCTA, K, aLD, aColOff,
                       Ah, Al, Bth, Btl);
            cp_commit();
            asm volatile("cp.async.wait_group 1;\n" ::: "memory");
        } else {
            asm volatile("cp.async.wait_group 0;\n" ::: "memory");
        }
        fence_proxy_async_cta();
        __syncthreads();

        if (warp == 0 && elect_one_pred()) {
            const uint32_t sa = tile + (uint32_t)(i & 1) * STG_SZ;
            const uint64_t dAh = make_desc(sa + STG_A_H);
            const uint64_t dAl = make_desc(sa + STG_A_L);
            const uint64_t dBh = make_desc(sa + STG_B_H);
            const uint64_t dBl = make_desc(sa + STG_B_L);
            #pragma unroll
            for (int ks = 0; ks < 4; ++ks) {
                const uint64_t ko = (uint64_t)(ks * 2);
                mma_f16_ss(tmem, dAh + ko, dBh + ko, (i > 0 || ks > 0) ? 1u : 0u);
                mma_f16_ss(tmem, dAh + ko, dBl + ko, 1u);
                mma_f16_ss(tmem, dAl + ko, dBh + ko, 1u);
            }
            tcgen05_commit(mbar);
        }
    }

    if (nk >= 2) mbar_wait(mbar, (uint32_t)((nk - 2) & 1));
    mbar_wait(mbar, (uint32_t)((nk - 1) & 1));
    TC_FENCE_AFTER();

    // epilogue: 8 warps x (32 rows, 128 cols)
    {
        const int sub = warp & 3;
        const int colbase = (warp >> 2) * 128;
        const int row = rowCTA + sub * 32 + lane;

        if (!diagMode) {
            #pragma unroll
            for (int cc = 0; cc < 4; ++cc) {
                const int c0 = colbase + cc * 32;
                uint32_t r[32];
                TC_LD_X32(r, tmem + (uint32_t)c0);
                TC_WAIT_LD();
                uint32_t ph[16], pl[16];
                #pragma unroll
                for (int c = 0; c < 32; c += 2) {
                    float v0 = tanhf(__uint_as_float(r[c])     + sbias[c0 + c]);
                    float v1 = tanhf(__uint_as_float(r[c + 1]) + sbias[c0 + c + 1]);
                    __nv_bfloat16 h0, l0, h1, l1;
                    split2(v0, h0, l0); split2(v1, h1, l1);
                    __nv_bfloat162 th = __halves2bfloat162(h0, h1);
                    __nv_bfloat162 tl = __halves2bfloat162(l0, l1);
                    ph[c >> 1] = *reinterpret_cast<uint32_t*>(&th);
                    pl[c >> 1] = *reinterpret_cast<uint32_t*>(&tl);
                }
                const size_t o = (size_t)row * NW + colCTA + c0;
                uint4* dh = reinterpret_cast<uint4*>(Ch + o);
                uint4* dl = reinterpret_cast<uint4*>(Cl + o);
                #pragma unroll
                for (int q = 0; q < 4; ++q) {
                    dh[q] = make_uint4(ph[4 * q], ph[4 * q + 1], ph[4 * q + 2], ph[4 * q + 3]);
                    dl[q] = make_uint4(pl[4 * q], pl[4 * q + 1], pl[4 * q + 2], pl[4 * q + 3]);
                }
            }
        } else {
            const int sel = (colCTA >= 512);
            const float* w4 = W4T + (size_t)sel * 32768 + (size_t)(row & 63) * 512
                            + (colCTA - sel * 512) + colbase;
            float p = 0.f;
            #pragma unroll
            for (int cc = 0; cc < 4; ++cc) {
                const int c0 = colbase + cc * 32;
                uint32_t r[32];
                TC_LD_X32(r, tmem + (uint32_t)c0);
                TC_WAIT_LD();
                #pragma unroll
                for (int c = 0; c < 32; ++c) {
                    float v = tanhf(__uint_as_float(r[c]) + sbias[c0 + c]);
                    p += v * w4[cc * 32 + c];
                }
            }
            atomicAdd((sel ? dtbuf : dsbuf) + row, p);
        }
        TC_FENCE_BEFORE();
    }

    __syncthreads();
    if (tid == 0) mbar_inval(mbar);
    __syncthreads();
    if (warp == 0) TC_DEALLOC(tmem, 256);

#else
    // =======================  mma.sync fallback  =======================
    extern __shared__ __align__(16) __nv_bfloat16 smem[];
    const int tid  = threadIdx.x;
    const int warp = tid >> 5, lane = tid & 31;
    const int wm = warp & 1, wn = warp >> 1;
    const int g  = lane >> 2, tg = lane & 3;
    const int rowCTA = blockIdx.y * 128;
    const int colBase256 = blockIdx.x * 256;
    const int aColOff = splitA ? (colBase256 & 512) : 0;

    for (int nh = 0; nh < 2; ++nh) {
        const int colCTA = colBase256 + nh * 128;

        float acc[4][4][4];
        #pragma unroll
        for (int a = 0; a < 4; ++a)
            #pragma unroll
            for (int b = 0; b < 4; ++b)
                #pragma unroll
                for (int c = 0; c < 4; ++c) acc[a][b][c] = 0.f;

        const int nk = K / 32;
        __syncthreads();
        load_tiles_fb(smem, 0, 0, rowCTA, colCTA, K, aLD, aColOff, Ah, Al, Bth, Btl);
        cp_commit();

        for (int kk = 0; kk < nk; ++kk) {
            if (kk + 1 < nk) {
                load_tiles_fb(smem, (kk + 1) & 1, (kk + 1) * 32, rowCTA, colCTA, K, aLD, aColOff,
                              Ah, Al, Bth, Btl);
                cp_commit();
                asm volatile("cp.async.wait_group 1;\n");
            } else {
                asm volatile("cp.async.wait_group 0;\n");
            }
            __syncthreads();

            const int st = kk & 1;
            const __nv_bfloat16* pAh = smem + (size_t)st * 128 * 40;
            const __nv_bfloat16* pAl = pAh + 2 * 128 * 40;
            const __nv_bfloat16* pBh = pAh + 4 * 128 * 40;
            const __nv_bfloat16* pBl = pAh + 6 * 128 * 40;

            #pragma unroll
            for (int kh = 0; kh < 2; ++kh) {
                const int k16 = kh * 16 + 2 * tg;
                uint32_t afh[4][4], afl[4][4];
                #pragma unroll
                for (int mt = 0; mt < 4; ++mt) {
                    const int r0 = (wm * 64 + mt * 16 + g) * 40 + k16;
                    const __nv_bfloat16* p = pAh + r0;
                    const __nv_bfloat16* q = pAl + r0;
                    afh[mt][0] = *(const uint32_t*)(p);
                    afh[mt][1] = *(const uint32_t*)(p + 8 * 40);
                    afh[mt][2] = *(const uint32_t*)(p + 8);
                    afh[mt][3] = *(const uint32_t*)(p + 8 * 40 + 8);
                    afl[mt][0] = *(const uint32_t*)(q);
                    afl[mt][1] = *(const uint32_t*)(q + 8 * 40);
                    afl[mt][2] = *(const uint32_t*)(q + 8);
                    afl[mt][3] = *(const uint32_t*)(q + 8 * 40 + 8);
                }
                #pragma unroll
                for (int nt = 0; nt < 4; ++nt) {
                    const int c0 = (wn * 32 + nt * 8 + g) * 40 + k16;
                    const __nv_bfloat16* pb = pBh + c0;
                    const __nv_bfloat16* qb = pBl + c0;
                    uint32_t bh[2] = { *(const uint32_t*)(pb), *(const uint32_t*)(pb + 8) };
                    uint32_t bl[2] = { *(const uint32_t*)(qb), *(const uint32_t*)(qb + 8) };
                    #pragma unroll
                    for (int mt = 0; mt < 4; ++mt) {
                        mma16816(acc[mt][nt], afh[mt], bh);
                        mma16816(acc[mt][nt], afh[mt], bl);
                        mma16816(acc[mt][nt], afl[mt], bh);
                    }
                }
            }
            __syncthreads();
        }

        #pragma unroll
        for (int mt = 0; mt < 4; ++mt) {
            const int r0 = rowCTA + wm * 64 + mt * 16 + g;
            #pragma unroll
            for (int nt = 0; nt < 4; ++nt) {
                const int c = colCTA + wn * 32 + nt * 8 + 2 * tg;
                const float bb0 = (c < 512) ? bias_s[c] : bias_t[c - 512];
                const float bb1 = (c + 1 < 512) ? bias_s[c + 1] : bias_t[c + 1 - 512];
                #pragma unroll
                for (int h = 0; h < 2; ++h) {
                    const int r = r0 + h * 8;
                    float v0 = tanhf(acc[mt][nt][2 * h + 0] + bb0);
                    float v1 = tanhf(acc[mt][nt][2 * h + 1] + bb1);
                    if (!diagMode) {
                        __nv_bfloat16 h0, l0, h1, l1;
                        split2(v0, h0, l0); split2(v1, h1, l1);
                        size_t off = (size_t)r * NW + c;
                        *reinterpret_cast<__nv_bfloat162*>(Ch + off) = __halves2bfloat162(h0, h1);
                        *reinterpret_cast<__nv_bfloat162*>(Cl + off) = __halves2bfloat162(l0, l1);
                    } else {
                        const int sel = (c >= 512);
                        const float* w4 = W4T + (size_t)sel * 32768 + (size_t)(r & 63) * 512
                                        + (c - sel * 512);
                        atomicAdd((sel ? dtbuf : dsbuf) + r, v0 * w4[0] + v1 * w4[1]);
                    }
                }
            }
        }
    }
#endif
}

// ---------------------------------------------------------------------------
// final combine: out = (x - dt) * exp(-ds)
// ---------------------------------------------------------------------------
__global__ void final_combine(const float* __restrict__ x, float* __restrict__ out) {
    const float* ds = (const float*)(g_scratch + OFF_DS);
    const float* dt = (const float*)(g_scratch + OFF_DT);
    int r = blockIdx.x * blockDim.x + threadIdx.x;
    if (r < R_) out[r] = (x[r] - dt[r]) * expf(-ds[r]);
}

// ---------------------------------------------------------------------------
// launch
// ---------------------------------------------------------------------------
extern "C" void kernel_launch(void* const* d_in, const int* in_sizes, int n_in,
                              void* d_out, int out_size) {
    (void)in_sizes; (void)n_in; (void)out_size;
    const float* x    = (const float*)d_in[0];
    const float* koop = (const float*)d_in[1];
    const float* W1[2] = { (const float*)d_in[2],  (const float*)d_in[10] };
    const float* b1[2] = { (const float*)d_in[3],  (const float*)d_in[11] };
    const float* W2[2] = { (const float*)d_in[4],  (const float*)d_in[12] };
    const float* b2[2] = { (const float*)d_in[5],  (const float*)d_in[13] };
    const float* W3[2] = { (const float*)d_in[6],  (const float*)d_in[14] };
    const float* b3[2] = { (const float*)d_in[7],  (const float*)d_in[15] };
    const float* W4[2] = { (const float*)d_in[8],  (const float*)d_in[16] };
    const float* b4[2] = { (const float*)d_in[9],  (const float*)d_in[17] };
    float* out = (float*)d_out;
    (void)b4;   // b4 folded below via final combine? (b4 contributes to diag dot)

    cudaFuncSetAttribute((const void*)gemm_t5,
                         cudaFuncAttributeMaxDynamicSharedMemorySize, GEMM_SMEM);

    // prep: Z split; combined weight regions (s rows 0-511, t rows 512-1023)
    split_z_kernel<<<B_, 256>>>(koop);
    for (int m = 0; m < 2; ++m) {
        split_weight<<<(512 * 64  + 255) / 256, 256>>>(W1[m], WOFF_1 + (size_t)m * 512 * 64,  64);
        split_weight<<<(512 * 512 + 255) / 256, 256>>>(W2[m], WOFF_2 + (size_t)m * 512 * 512, 512);
        split_weight<<<(512 * 512 + 255) / 256, 256>>>(W3[m], WOFF_3 + (size_t)m * 512 * 512, 512);
        transpose_w4<<<(64 * 512 + 255) / 256, 256>>>(W4[m], m);
    }

    // zero ds/dt accumulators (graph-capturable async memset, same stream)
    void* base = nullptr;
    cudaGetSymbolAddress(&base, g_scratch);
    cudaMemsetAsync((unsigned char*)base + OFF_DS, 0, 2 * SZ_DS, 0);

    dim3 grid(NW / 256, R_ / 128);  // (4, 1024)
    // layer 1: Z (K=64, aLD=64) -> H0 (1024-wide)
    gemm_t5<<<grid, 256, GEMM_SMEM>>>(OFF_ZH, OFF_ZL, 64, 0, WOFF_1,
                                      b1[0], b1[1], OFF_H0H, OFF_H0L, 64, 0);
    // layer 2: H0 -> H1 (block-diagonal via aColOff)
    gemm_t5<<<grid, 256, GEMM_SMEM>>>(OFF_H0H, OFF_H0L, NW, 1, WOFF_2,
                                      b2[0], b2[1], OFF_H1H, OFF_H1L, 512, 0);
    // layer 3: H1 -> diag dots (no C store)
    gemm_t5<<<grid, 256, GEMM_SMEM>>>(OFF_H1H, OFF_H1L, NW, 1, WOFF_3,
                                      b3[0], b3[1], OFF_H0H, OFF_H0L, 512, 1);

    // add b4 diag contribution + final combine:
    // ds[r] += b4_s[r%64], dt[r] += b4_t[r%64] folded into combine kernel:
    // out = (x - (dt + b4_t)) * exp(-(ds + b4_s))
    // implemented by a small lambda-style kernel below
    {
        struct K { const float *x, *b4s, *b4t; float* out; };
        // use a dedicated kernel (defined via final_combine2 pattern)
        extern __global__ void final_combine2(const float*, const float*, const float*, float*);
        final_combine2<<<R_ / 256, 256>>>(x, b4[0], b4[1], out);
    }
}

// out = (x - (dt + b4_t[r%64])) * exp(-(ds + b4_s[r%64]))
__global__ void final_combine2(const float* __restrict__ x,
                               const float* __restrict__ b4s,
                               const float* __restrict__ b4t,
                               float* __restrict__ out) {
    const float* ds = (const float*)(g_scratch + OFF_DS);
    const float* dt = (const float*)(g_scratch + OFF_DT);
    int r = blockIdx.x * blockDim.x + threadIdx.x;
    if (r < R_) {
        int i = r & 63;
        float s = ds[r] + b4s[i];
        float t = dt[r] + b4t[i];
        out[r] = (x[r] - t) * expf(-s);
    }
}